// round 5
// baseline (speedup 1.0000x reference)
#include <cuda_runtime.h>
#include <math.h>

#define N_PTS   8192
#define GDIM    8
#define NCELLS  (GDIM * GDIM * GDIM)          // 512
#define INV_H   26.666666666666668f           // 1 / 0.0375
#define H2      0.00140625f                   // 0.0375^2
#define THR2    4.0e-4f                       // 0.02^2
#define BIGF    1.0e30f
#define PPT     (N_PTS / 1024)                // 8 points per thread in bin_k

// ---------------- device scratch (no allocations allowed) ----------------
__device__ int    g_startc[NCELLS + 1];
__device__ int    g_orig[N_PTS];      // sorted slot -> original index
__device__ float4 g_sp[N_PTS];        // sorted positions (x,y,z,|p|^2)
__device__ float4 g_sq[N_PTS];        // sorted quaternions
__device__ float  g_density[N_PTS];   // indexed by sorted slot
__device__ float  g_align_sum[N_PTS];
__device__ float  g_align_cnt[N_PTS];

// ---------------- helpers ----------------
__device__ __forceinline__ void insert9(float (&t)[9], float d) {
    if (d < t[8]) {
        t[8] = d;
        #pragma unroll
        for (int k = 8; k > 0; --k) {
            float lo = fminf(t[k - 1], t[k]);
            float hi = fmaxf(t[k - 1], t[k]);
            t[k - 1] = lo;
            t[k]     = hi;
        }
    }
}

// Warp-collective: extract the 9 smallest d2 across the warp's per-lane sorted
// lists; return mean of distances excluding the global min (self-distance).
// Reports the 9th-smallest d2 (for sentinel validity checking). Destroys t.
__device__ __forceinline__ float knn_mean(float (&t)[9], int lane, float* ninth_d2) {
    float sum = 0.0f, mn = 0.0f, last = 0.0f;
    #pragma unroll
    for (int r = 0; r < 9; ++r) {
        float cand = t[0];
        float v = cand;
        #pragma unroll
        for (int off = 16; off > 0; off >>= 1)
            v = fminf(v, __shfl_xor_sync(0xffffffffu, v, off));
        unsigned m = __ballot_sync(0xffffffffu, cand == v);
        if (lane == (__ffs(m) - 1)) {
            #pragma unroll
            for (int k = 0; k < 8; ++k) t[k] = t[k + 1];
            t[8] = BIGF;
        }
        float d = sqrtf(fmaxf(v, 0.0f) + 1e-12f);
        if (r == 0) mn = d;
        if (r == 8) last = v;
        sum += d;
    }
    *ninth_d2 = last;
    return (sum - mn) * 0.125f;
}

// ---------------- fused binning: zero + count + scan + scatter ----------------
__global__ __launch_bounds__(1024)
void bin_k(const float* __restrict__ pos, const float4* __restrict__ rot) {
    __shared__ int s_cnt[NCELLS];
    __shared__ int s_sc[NCELLS];
    __shared__ int s_start[NCELLS + 1];

    const int t = threadIdx.x;
    if (t < NCELLS) s_cnt[t] = 0;
    __syncthreads();

    int   cid[PPT], rank[PPT];
    float px[PPT], py[PPT], pz[PPT];
    #pragma unroll
    for (int k = 0; k < PPT; ++k) {
        int i = t + k * 1024;
        float x = pos[3 * i + 0], y = pos[3 * i + 1], z = pos[3 * i + 2];
        px[k] = x; py[k] = y; pz[k] = z;
        int cx = min(GDIM - 1, max(0, (int)(x * INV_H)));
        int cy = min(GDIM - 1, max(0, (int)(y * INV_H)));
        int cz = min(GDIM - 1, max(0, (int)(z * INV_H)));
        cid[k]  = (cz * GDIM + cy) * GDIM + cx;
        rank[k] = atomicAdd(&s_cnt[cid[k]], 1);
    }
    __syncthreads();

    // inclusive scan of 512 counts (Hillis-Steele; all threads hit barriers)
    if (t < NCELLS) s_sc[t] = s_cnt[t];
    __syncthreads();
    #pragma unroll
    for (int off = 1; off < NCELLS; off <<= 1) {
        int add = 0;
        if (t < NCELLS && t >= off) add = s_sc[t - off];
        __syncthreads();
        if (t < NCELLS) s_sc[t] += add;
        __syncthreads();
    }
    if (t < NCELLS) {
        s_start[t + 1] = s_sc[t];
        g_startc[t + 1] = s_sc[t];
    }
    if (t == 0) { s_start[0] = 0; g_startc[0] = 0; }
    __syncthreads();

    #pragma unroll
    for (int k = 0; k < PPT; ++k) {
        int i = t + k * 1024;
        int dst = s_start[cid[k]] + rank[k];
        float x = px[k], y = py[k], z = pz[k];
        g_sp[dst]   = make_float4(x, y, z, fmaf(x, x, fmaf(y, y, z * z)));
        g_sq[dst]   = rot[i];
        g_orig[dst] = i;
    }
}

// ---------------- main: one warp per sorted row, fallback fused ----------------
__global__ __launch_bounds__(256)
void main_k(const float* __restrict__ opacity) {
    const int s    = (blockIdx.x * blockDim.x + threadIdx.x) >> 5;
    const int lane = threadIdx.x & 31;

    const float4 P = g_sp[s];
    const float4 Q = g_sq[s];
    int cx = min(GDIM - 1, max(0, (int)(P.x * INV_H)));
    int cy = min(GDIM - 1, max(0, (int)(P.y * INV_H)));
    int cz = min(GDIM - 1, max(0, (int)(P.z * INV_H)));

    float t[9];
    #pragma unroll
    for (int k = 0; k < 9; ++k) t[k] = H2;   // sentinel: survives => <9 nbrs in h
    float asum = 0.0f, acnt = 0.0f;

    const int x0 = max(cx - 1, 0), x1 = min(cx + 1, GDIM - 1);
    const int y0 = max(cy - 1, 0), y1 = min(cy + 1, GDIM - 1);
    const int z0 = max(cz - 1, 0), z1 = min(cz + 1, GDIM - 1);

    for (int z = z0; z <= z1; ++z) {
        for (int y = y0; y <= y1; ++y) {
            int rowb = (z * GDIM + y) * GDIM;
            int jb = g_startc[rowb + x0];
            int je = g_startc[rowb + x1 + 1];
            for (int j = jb + lane; j < je; j += 32) {
                float4 p = g_sp[j];
                float dot = fmaf(P.x, p.x, fmaf(P.y, p.y, P.z * p.z));
                float d2  = fmaf(-2.0f, dot, P.w + p.w);
                insert9(t, d2);
                if (d2 < THR2 && j != s) {        // alignment exact: 0.02 < h
                    float4 q = g_sq[j];
                    float qd = fmaf(Q.x, q.x, fmaf(Q.y, q.y, fmaf(Q.z, q.z, Q.w * q.w)));
                    asum += 1.0f - fabsf(qd);
                    acnt += 1.0f;
                }
            }
        }
    }

    #pragma unroll
    for (int off = 16; off > 0; off >>= 1) {
        asum += __shfl_xor_sync(0xffffffffu, asum, off);
        acnt += __shfl_xor_sync(0xffffffffu, acnt, off);
    }

    float ninth;
    float knn = knn_mean(t, lane, &ninth);      // warp-uniform results

    if (ninth >= H2) {
        // rare (boundary rows lacking 9 nbrs within h): brute-force, warp-uniform
        #pragma unroll
        for (int k = 0; k < 9; ++k) t[k] = BIGF;
        for (int j = lane; j < N_PTS; j += 32) {
            float4 p = g_sp[j];
            float dot = fmaf(P.x, p.x, fmaf(P.y, p.y, P.z * p.z));
            float d2  = fmaf(-2.0f, dot, P.w + p.w);
            insert9(t, d2);
        }
        knn = knn_mean(t, lane, &ninth);
    }

    if (lane == 0) {
        g_align_sum[s] = asum;
        g_align_cnt[s] = acnt;
        g_density[s]   = fabsf(knn - 0.01f) * opacity[g_orig[s]];
    }
}

// ---------------- final: flatness + total reduction, one block ----------------
__global__ __launch_bounds__(1024)
void final_k(const float* __restrict__ scales, float* __restrict__ out) {
    __shared__ float sf[32][4];
    const int tid = threadIdx.x, lane = tid & 31, wid = tid >> 5;

    float F = 0.0f, D = 0.0f, A = 0.0f, C = 0.0f;
    for (int i = tid; i < N_PTS; i += 1024) {
        float a = expf(scales[3 * i + 0]);
        float b = expf(scales[3 * i + 1]);
        float c = expf(scales[3 * i + 2]);
        float tt;
        if (a > b) { tt = a; a = b; b = tt; }
        if (b > c) { tt = b; b = c; c = tt; }
        if (a > b) { tt = a; a = b; b = tt; }
        F += logf(c / (a + 1e-8f) + 1e-8f) + 0.1f / (fabsf(c - b) + 0.001f);
        D += g_density[i];
        A += g_align_sum[i];
        C += g_align_cnt[i];
    }
    #pragma unroll
    for (int off = 16; off > 0; off >>= 1) {
        F += __shfl_down_sync(0xffffffffu, F, off);
        D += __shfl_down_sync(0xffffffffu, D, off);
        A += __shfl_down_sync(0xffffffffu, A, off);
        C += __shfl_down_sync(0xffffffffu, C, off);
    }
    if (lane == 0) { sf[wid][0] = F; sf[wid][1] = D; sf[wid][2] = A; sf[wid][3] = C; }
    __syncthreads();
    if (wid == 0) {
        F = sf[lane][0]; D = sf[lane][1]; A = sf[lane][2]; C = sf[lane][3];
        #pragma unroll
        for (int off = 16; off > 0; off >>= 1) {
            F += __shfl_down_sync(0xffffffffu, F, off);
            D += __shfl_down_sync(0xffffffffu, D, off);
            A += __shfl_down_sync(0xffffffffu, A, off);
            C += __shfl_down_sync(0xffffffffu, C, off);
        }
        if (lane == 0) {
            float flatness_loss  = -(F / (float)N_PTS);
            float alignment_loss = (C > 0.0f) ? (A / C) : 0.0f;
            float density_loss   = D / (float)N_PTS;
            out[0] = flatness_loss + 0.5f * alignment_loss + 0.2f * density_loss;
        }
    }
}

// ---------------- launch ----------------
extern "C" void kernel_launch(void* const* d_in, const int* in_sizes, int n_in,
                              void* d_out, int out_size) {
    const float*  positions = (const float*)d_in[0];
    const float4* rotations = (const float4*)d_in[1];
    const float*  scales    = (const float*)d_in[2];
    const float*  opacity   = (const float*)d_in[3];
    float* out = (float*)d_out;

    bin_k<<<1, 1024>>>(positions, rotations);
    main_k<<<N_PTS / 8, 256>>>(opacity);     // 1 warp per sorted row
    final_k<<<1, 1024>>>(scales, out);
}

// round 6
// speedup vs baseline: 1.1896x; 1.1896x over previous
#include <cuda_runtime.h>
#include <math.h>

#define N_PTS   8192
#define GDIM    8
#define NCELLS  (GDIM * GDIM * GDIM)          // 512
#define CELL_H  0.0375f
#define INV_H   26.666666666666668f           // 1 / 0.0375
#define H2      0.00140625f                   // 0.0375^2
#define THR2    4.0e-4f                       // 0.02^2
#define BIGF    1.0e30f
#define CAP     96                            // bucket capacity (mean 16/cell)
#define SMEM_CAND 1088                        // smem candidate capacity

// ---------------- device scratch (no allocations allowed) ----------------
__device__ int    g_cnt[NCELLS];              // zero-init at load; final_k re-zeroes
__device__ float4 g_bpos[NCELLS * CAP];       // bucketed (x,y,z,|p|^2)
__device__ float4 g_bquat[NCELLS * CAP];      // bucketed quaternions
__device__ int    g_borig[NCELLS * CAP];      // bucketed original indices
__device__ float  g_flat[N_PTS];              // per-point flatness term
__device__ float  g_density[N_PTS];
__device__ float  g_align_sum[N_PTS];
__device__ float  g_align_cnt[N_PTS];

// ---------------- helpers ----------------
__device__ __forceinline__ void insert9(float (&t)[9], float d) {
    if (d < t[8]) {
        t[8] = d;
        #pragma unroll
        for (int k = 8; k > 0; --k) {
            float lo = fminf(t[k - 1], t[k]);
            float hi = fmaxf(t[k - 1], t[k]);
            t[k - 1] = lo;
            t[k]     = hi;
        }
    }
}

// Warp-collective: extract 9 smallest d2 across the warp's per-lane sorted
// lists; return mean of distances excluding the global min (self-distance).
// Reports the 9th-smallest d2 (sentinel validity check). Destroys t.
__device__ __forceinline__ float knn_mean(float (&t)[9], int lane, float* ninth_d2) {
    float sum = 0.0f, mn = 0.0f, last = 0.0f;
    #pragma unroll
    for (int r = 0; r < 9; ++r) {
        float cand = t[0];
        float v = cand;
        #pragma unroll
        for (int off = 16; off > 0; off >>= 1)
            v = fminf(v, __shfl_xor_sync(0xffffffffu, v, off));
        unsigned m = __ballot_sync(0xffffffffu, cand == v);
        if (lane == (__ffs(m) - 1)) {
            #pragma unroll
            for (int k = 0; k < 8; ++k) t[k] = t[k + 1];
            t[8] = BIGF;
        }
        float d = sqrtf(fmaxf(v, 0.0f) + 1e-12f);
        if (r == 0) mn = d;
        if (r == 8) last = v;
        sum += d;
    }
    *ninth_d2 = last;
    return (sum - mn) * 0.125f;
}

// ---------------- scatter: bucket points + per-point flatness ----------------
__global__ __launch_bounds__(256)
void scatter_k(const float* __restrict__ pos,
               const float4* __restrict__ rot,
               const float* __restrict__ scales) {
    int i = blockIdx.x * 256 + threadIdx.x;

    float x = pos[3 * i + 0], y = pos[3 * i + 1], z = pos[3 * i + 2];
    int cx = min(GDIM - 1, max(0, (int)(x * INV_H)));
    int cy = min(GDIM - 1, max(0, (int)(y * INV_H)));
    int cz = min(GDIM - 1, max(0, (int)(z * INV_H)));
    int cid = (cz * GDIM + cy) * GDIM + cx;

    int slot = atomicAdd(&g_cnt[cid], 1);
    if (slot < CAP) {
        int dst = cid * CAP + slot;
        g_bpos[dst]  = make_float4(x, y, z, fmaf(x, x, fmaf(y, y, z * z)));
        g_bquat[dst] = rot[i];
        g_borig[dst] = i;
    }

    // flatness term (parallel, off the critical single-block path)
    float a = expf(scales[3 * i + 0]);
    float b = expf(scales[3 * i + 1]);
    float c = expf(scales[3 * i + 2]);
    float tt;
    if (a > b) { tt = a; a = b; b = tt; }
    if (b > c) { tt = b; b = c; c = tt; }
    if (a > b) { tt = a; a = b; b = tt; }
    g_flat[i] = logf(c / (a + 1e-8f) + 1e-8f) + 0.1f / (fabsf(c - b) + 0.001f);
}

// ---------------- main: one block per cell, smem candidate cache ----------------
__global__ __launch_bounds__(128)
void main_k(const float* __restrict__ opacity) {
    __shared__ float4 s_p[SMEM_CAND];
    __shared__ float4 s_q[SMEM_CAND];
    __shared__ int    s_id[SMEM_CAND];

    const int cell = blockIdx.x;
    const int tid  = threadIdx.x;
    const int lane = tid & 31;
    const int warp = tid >> 5;

    const int cx = cell & (GDIM - 1);
    const int cy = (cell >> 3) & (GDIM - 1);
    const int cz = cell >> 6;
    const int x0 = max(cx - 1, 0), x1 = min(cx + 1, GDIM - 1);
    const int y0 = max(cy - 1, 0), y1 = min(cy + 1, GDIM - 1);
    const int z0 = max(cz - 1, 0), z1 = min(cz + 1, GDIM - 1);

    // total candidate count (uniform across threads; broadcast loads)
    int total = 0;
    for (int z = z0; z <= z1; ++z)
        for (int y = y0; y <= y1; ++y)
            for (int x = x0; x <= x1; ++x)
                total += min(g_cnt[(z * GDIM + y) * GDIM + x], CAP);

    const bool oversize = (total > SMEM_CAND);

    if (!oversize) {
        int off = 0;
        for (int z = z0; z <= z1; ++z)
            for (int y = y0; y <= y1; ++y)
                for (int x = x0; x <= x1; ++x) {
                    int c2 = (z * GDIM + y) * GDIM + x;
                    int cnt2 = min(g_cnt[c2], CAP);
                    int b2 = c2 * CAP;
                    for (int j = tid; j < cnt2; j += 128) {
                        s_p[off + j]  = g_bpos[b2 + j];
                        s_q[off + j]  = g_bquat[b2 + j];
                        s_id[off + j] = g_borig[b2 + j];
                    }
                    off += cnt2;
                }
    }
    __syncthreads();

    const int myCnt = min(g_cnt[cell], CAP);
    const int mybase = cell * CAP;

    for (int r = warp; r < myCnt; r += 4) {
        const float4 P = g_bpos[mybase + r];
        const float4 Q = g_bquat[mybase + r];
        const int myid = g_borig[mybase + r];

        float t[9];
        #pragma unroll
        for (int k = 0; k < 9; ++k) t[k] = H2;     // sentinel: survives => <9 in h
        float asum = 0.0f, acnt = 0.0f;

        if (!oversize) {
            for (int j = lane; j < total; j += 32) {
                float4 p = s_p[j];
                float dot = fmaf(P.x, p.x, fmaf(P.y, p.y, P.z * p.z));
                float d2  = fmaf(-2.0f, dot, P.w + p.w);
                insert9(t, d2);
                if (d2 < THR2 && s_id[j] != myid) {  // alignment exact: 0.02 < h
                    float4 q = s_q[j];
                    float qd = fmaf(Q.x, q.x, fmaf(Q.y, q.y, fmaf(Q.z, q.z, Q.w * q.w)));
                    asum += 1.0f - fabsf(qd);
                    acnt += 1.0f;
                }
            }
        } else {
            for (int z = z0; z <= z1; ++z)
                for (int y = y0; y <= y1; ++y)
                    for (int x = x0; x <= x1; ++x) {
                        int c2 = (z * GDIM + y) * GDIM + x;
                        int cnt2 = min(g_cnt[c2], CAP);
                        int b2 = c2 * CAP;
                        for (int j = lane; j < cnt2; j += 32) {
                            float4 p = g_bpos[b2 + j];
                            float dot = fmaf(P.x, p.x, fmaf(P.y, p.y, P.z * p.z));
                            float d2  = fmaf(-2.0f, dot, P.w + p.w);
                            insert9(t, d2);
                            if (d2 < THR2 && g_borig[b2 + j] != myid) {
                                float4 q = g_bquat[b2 + j];
                                float qd = fmaf(Q.x, q.x, fmaf(Q.y, q.y, fmaf(Q.z, q.z, Q.w * q.w)));
                                asum += 1.0f - fabsf(qd);
                                acnt += 1.0f;
                            }
                        }
                    }
        }

        #pragma unroll
        for (int off2 = 16; off2 > 0; off2 >>= 1) {
            asum += __shfl_xor_sync(0xffffffffu, asum, off2);
            acnt += __shfl_xor_sync(0xffffffffu, acnt, off2);
        }

        float ninth;
        float knn = knn_mean(t, lane, &ninth);      // warp-uniform

        // radius-expanding exact fallback (rare boundary rows)
        int radius = 1;
        bool done = (ninth < H2);
        while (!done && radius < 16) {
            radius++;
            float sent  = CELL_H * (float)radius;
            float sent2 = sent * sent;
            int ex0 = max(cx - radius, 0), ex1 = min(cx + radius, GDIM - 1);
            int ey0 = max(cy - radius, 0), ey1 = min(cy + radius, GDIM - 1);
            int ez0 = max(cz - radius, 0), ez1 = min(cz + radius, GDIM - 1);
            #pragma unroll
            for (int k = 0; k < 9; ++k) t[k] = sent2;
            for (int z = ez0; z <= ez1; ++z)
                for (int y = ey0; y <= ey1; ++y)
                    for (int x = ex0; x <= ex1; ++x) {
                        int c2 = (z * GDIM + y) * GDIM + x;
                        int cnt2 = min(g_cnt[c2], CAP);
                        int b2 = c2 * CAP;
                        for (int j = lane; j < cnt2; j += 32) {
                            float4 p = g_bpos[b2 + j];
                            float dot = fmaf(P.x, p.x, fmaf(P.y, p.y, P.z * p.z));
                            float d2  = fmaf(-2.0f, dot, P.w + p.w);
                            insert9(t, d2);
                        }
                    }
            knn = knn_mean(t, lane, &ninth);
            bool full = (ex0 == 0) && (ex1 == GDIM - 1) && (ey0 == 0) &&
                        (ey1 == GDIM - 1) && (ez0 == 0) && (ez1 == GDIM - 1);
            done = (ninth < sent2) || full;
        }

        if (lane == 0) {
            g_align_sum[myid] = asum;
            g_align_cnt[myid] = acnt;
            g_density[myid]   = fabsf(knn - 0.01f) * opacity[myid];
        }
    }
}

// ---------------- final: pure reduction + counter re-zero ----------------
__global__ __launch_bounds__(1024)
void final_k(float* __restrict__ out) {
    __shared__ float sf[32][4];
    const int tid = threadIdx.x, lane = tid & 31, wid = tid >> 5;

    float F = 0.0f, D = 0.0f, A = 0.0f, C = 0.0f;
    #pragma unroll
    for (int k = 0; k < N_PTS / 1024; ++k) {
        int i = tid + k * 1024;
        F += g_flat[i];
        D += g_density[i];
        A += g_align_sum[i];
        C += g_align_cnt[i];
    }
    #pragma unroll
    for (int off = 16; off > 0; off >>= 1) {
        F += __shfl_down_sync(0xffffffffu, F, off);
        D += __shfl_down_sync(0xffffffffu, D, off);
        A += __shfl_down_sync(0xffffffffu, A, off);
        C += __shfl_down_sync(0xffffffffu, C, off);
    }
    if (lane == 0) { sf[wid][0] = F; sf[wid][1] = D; sf[wid][2] = A; sf[wid][3] = C; }
    __syncthreads();
    if (wid == 0) {
        F = sf[lane][0]; D = sf[lane][1]; A = sf[lane][2]; C = sf[lane][3];
        #pragma unroll
        for (int off = 16; off > 0; off >>= 1) {
            F += __shfl_down_sync(0xffffffffu, F, off);
            D += __shfl_down_sync(0xffffffffu, D, off);
            A += __shfl_down_sync(0xffffffffu, A, off);
            C += __shfl_down_sync(0xffffffffu, C, off);
        }
        if (lane == 0) {
            float flatness_loss  = -(F / (float)N_PTS);
            float alignment_loss = (C > 0.0f) ? (A / C) : 0.0f;
            float density_loss   = D / (float)N_PTS;
            out[0] = flatness_loss + 0.5f * alignment_loss + 0.2f * density_loss;
        }
    }

    // restore bucket-counter invariant for the next graph replay
    if (tid < NCELLS) g_cnt[tid] = 0;
}

// ---------------- launch ----------------
extern "C" void kernel_launch(void* const* d_in, const int* in_sizes, int n_in,
                              void* d_out, int out_size) {
    const float*  positions = (const float*)d_in[0];
    const float4* rotations = (const float4*)d_in[1];
    const float*  scales    = (const float*)d_in[2];
    const float*  opacity   = (const float*)d_in[3];
    float* out = (float*)d_out;

    scatter_k<<<N_PTS / 256, 256>>>(positions, rotations, scales);
    main_k<<<NCELLS, 128>>>(opacity);
    final_k<<<1, 1024>>>(out);
}

// round 7
// speedup vs baseline: 1.2470x; 1.0483x over previous
#include <cuda_runtime.h>
#include <math.h>

#define N_PTS   8192
#define GDIM    8
#define NCELLS  512
#define CELL_H  0.0375f
#define INV_H   26.666666666666668f           // 1 / 0.0375
#define H2      0.00140625f                   // 0.0375^2
#define THR2    4.0e-4f                       // 0.02^2
#define BIGF    1.0e30f
#define CAP     96                            // bucket capacity (mean 16/cell)
#define SMEM_CAND 1088                        // smem candidate capacity

// ---------------- device scratch (no allocations allowed) ----------------
__device__ int    g_cnt[NCELLS];              // zero-init; last block re-zeroes
__device__ int    g_done;                     // zero-init; last block re-zeroes
__device__ float4 g_bpos[NCELLS * CAP];       // bucketed (x,y,z,|p|^2)
__device__ float4 g_bquat[NCELLS * CAP];      // bucketed quaternions
__device__ int    g_borig[NCELLS * CAP];      // bucketed original indices
__device__ float  g_flat[N_PTS];              // per-point flatness term
__device__ float4 g_part[NCELLS];             // per-block partials (F,D,A,C)

// ---------------- helpers ----------------
__device__ __forceinline__ void insert9(float (&t)[9], float d) {
    if (d < t[8]) {
        t[8] = d;
        #pragma unroll
        for (int k = 8; k > 0; --k) {
            float lo = fminf(t[k - 1], t[k]);
            float hi = fmaxf(t[k - 1], t[k]);
            t[k - 1] = lo;
            t[k]     = hi;
        }
    }
}

// Warp-collective: extract 9 smallest d2 across per-lane sorted lists; return
// mean of distances excluding global min (self). Reports 9th-smallest d2.
__device__ __forceinline__ float knn_mean(float (&t)[9], int lane, float* ninth_d2) {
    float sum = 0.0f, mn = 0.0f, last = 0.0f;
    #pragma unroll
    for (int r = 0; r < 9; ++r) {
        float cand = t[0];
        float v = cand;
        #pragma unroll
        for (int off = 16; off > 0; off >>= 1)
            v = fminf(v, __shfl_xor_sync(0xffffffffu, v, off));
        unsigned m = __ballot_sync(0xffffffffu, cand == v);
        if (lane == (__ffs(m) - 1)) {
            #pragma unroll
            for (int k = 0; k < 8; ++k) t[k] = t[k + 1];
            t[8] = BIGF;
        }
        float d = sqrtf(fmaxf(v, 0.0f) + 1e-12f);
        if (r == 0) mn = d;
        if (r == 8) last = v;
        sum += d;
    }
    *ninth_d2 = last;
    return (sum - mn) * 0.125f;
}

// ---------------- scatter: bucket points + per-point flatness ----------------
__global__ __launch_bounds__(256)
void scatter_k(const float* __restrict__ pos,
               const float4* __restrict__ rot,
               const float* __restrict__ scales) {
    int i = blockIdx.x * 256 + threadIdx.x;

    float x = pos[3 * i + 0], y = pos[3 * i + 1], z = pos[3 * i + 2];
    int cx = min(GDIM - 1, max(0, (int)(x * INV_H)));
    int cy = min(GDIM - 1, max(0, (int)(y * INV_H)));
    int cz = min(GDIM - 1, max(0, (int)(z * INV_H)));
    int cid = (cz * GDIM + cy) * GDIM + cx;

    int slot = atomicAdd(&g_cnt[cid], 1);
    if (slot < CAP) {
        int dst = cid * CAP + slot;
        g_bpos[dst]  = make_float4(x, y, z, fmaf(x, x, fmaf(y, y, z * z)));
        g_bquat[dst] = rot[i];
        g_borig[dst] = i;
    }

    float a = expf(scales[3 * i + 0]);
    float b = expf(scales[3 * i + 1]);
    float c = expf(scales[3 * i + 2]);
    float tt;
    if (a > b) { tt = a; a = b; b = tt; }
    if (b > c) { tt = b; b = c; c = tt; }
    if (a > b) { tt = a; a = b; b = tt; }
    g_flat[i] = logf(c / (a + 1e-8f) + 1e-8f) + 0.1f / (fabsf(c - b) + 0.001f);
}

// ---------------- main: block per cell; fused final reduction ----------------
__global__ __launch_bounds__(256)
void main_k(const float* __restrict__ opacity, float* __restrict__ out) {
    __shared__ float4 s_p[SMEM_CAND];
    __shared__ float4 s_q[SMEM_CAND];
    __shared__ int    s_id[SMEM_CAND];
    __shared__ int    s_off[28];              // prefix offsets (s_off[0]=0)
    __shared__ int    s_base[27];             // bucket base per neighbor cell
    __shared__ float  s_part[8][4];
    __shared__ float  s_red[8][4];
    __shared__ int    s_is_last;

    const int cell = blockIdx.x;
    const int tid  = threadIdx.x;
    const int lane = tid & 31;
    const int warp = tid >> 5;

    const int cx = cell & 7, cy = (cell >> 3) & 7, cz = cell >> 6;
    const int x0 = max(cx - 1, 0), x1 = min(cx + 1, 7);
    const int y0 = max(cy - 1, 0), y1 = min(cy + 1, 7);
    const int z0 = max(cz - 1, 0), z1 = min(cz + 1, 7);
    const int nx = x1 - x0 + 1, ny = y1 - y0 + 1, nz = z1 - z0 + 1;
    const int ncells = nx * ny * nz;

    // warp 0: parallel count read + inclusive scan -> offsets
    if (tid < 32) {
        int cnt2 = 0;
        if (tid < ncells) {
            int lx = tid % nx, rem = tid / nx;
            int ly = rem % ny, lz = rem / ny;
            int cid = ((z0 + lz) * GDIM + (y0 + ly)) * GDIM + (x0 + lx);
            cnt2 = min(g_cnt[cid], CAP);
            s_base[tid] = cid * CAP;
        }
        int v = cnt2;
        #pragma unroll
        for (int off = 1; off < 32; off <<= 1) {
            int u = __shfl_up_sync(0xffffffffu, v, off);
            if (lane >= off) v += u;
        }
        if (tid < 27) s_off[tid + 1] = v;     // lanes >= ncells carry total
        if (tid == 0) s_off[0] = 0;
    }
    __syncthreads();

    const int total = s_off[27];
    const bool oversize = (total > SMEM_CAND);

    // flat parallel fill: binary-search source cell per candidate
    if (!oversize) {
        for (int idx = tid; idx < total; idx += 256) {
            int lo = 0, hi = 27;
            #pragma unroll
            for (int stp = 0; stp < 5; ++stp) {
                int mid = (lo + hi) >> 1;
                if (s_off[mid + 1] > idx) hi = mid; else lo = mid + 1;
            }
            int src = s_base[lo] + (idx - s_off[lo]);
            s_p[idx]  = g_bpos[src];
            s_q[idx]  = g_bquat[src];
            s_id[idx] = g_borig[src];
        }
    }
    __syncthreads();

    const int hc = (cx - x0) + nx * ((cy - y0) + ny * (cz - z0));  // home cell idx
    const int ho = s_off[hc];
    const int myCnt = s_off[hc + 1] - ho;

    float Fp = 0.0f, Dp = 0.0f, Ap = 0.0f, Cp = 0.0f;

    for (int r = warp; r < myCnt; r += 8) {
        float4 P, Q; int myid;
        if (!oversize) { P = s_p[ho + r]; Q = s_q[ho + r]; myid = s_id[ho + r]; }
        else { int src = cell * CAP + r; P = g_bpos[src]; Q = g_bquat[src]; myid = g_borig[src]; }

        float t[9];
        #pragma unroll
        for (int k = 0; k < 9; ++k) t[k] = H2;   // sentinel: survives => <9 in h
        float asum = 0.0f, acnt = 0.0f;

        if (!oversize) {
            for (int j = lane; j < total; j += 32) {
                float4 p = s_p[j];
                float dot = fmaf(P.x, p.x, fmaf(P.y, p.y, P.z * p.z));
                float d2  = fmaf(-2.0f, dot, P.w + p.w);
                insert9(t, d2);
                if (d2 < THR2 && s_id[j] != myid) {   // alignment exact: 0.02 < h
                    float4 q = s_q[j];
                    float qd = fmaf(Q.x, q.x, fmaf(Q.y, q.y, fmaf(Q.z, q.z, Q.w * q.w)));
                    asum += 1.0f - fabsf(qd);
                    acnt += 1.0f;
                }
            }
        } else {
            for (int c = 0; c < ncells; ++c) {
                int cnt2 = s_off[c + 1] - s_off[c];
                int b2 = s_base[c];
                for (int j = lane; j < cnt2; j += 32) {
                    float4 p = g_bpos[b2 + j];
                    float dot = fmaf(P.x, p.x, fmaf(P.y, p.y, P.z * p.z));
                    float d2  = fmaf(-2.0f, dot, P.w + p.w);
                    insert9(t, d2);
                    if (d2 < THR2 && g_borig[b2 + j] != myid) {
                        float4 q = g_bquat[b2 + j];
                        float qd = fmaf(Q.x, q.x, fmaf(Q.y, q.y, fmaf(Q.z, q.z, Q.w * q.w)));
                        asum += 1.0f - fabsf(qd);
                        acnt += 1.0f;
                    }
                }
            }
        }

        #pragma unroll
        for (int o = 16; o > 0; o >>= 1) {
            asum += __shfl_xor_sync(0xffffffffu, asum, o);
            acnt += __shfl_xor_sync(0xffffffffu, acnt, o);
        }

        float ninth;
        float knn = knn_mean(t, lane, &ninth);       // warp-uniform

        // radius-expanding exact fallback (rare boundary rows)
        int radius = 1;
        bool done = (ninth < H2);
        while (!done && radius < 16) {
            radius++;
            float sent  = CELL_H * (float)radius;
            float sent2 = sent * sent;
            int ex0 = max(cx - radius, 0), ex1 = min(cx + radius, 7);
            int ey0 = max(cy - radius, 0), ey1 = min(cy + radius, 7);
            int ez0 = max(cz - radius, 0), ez1 = min(cz + radius, 7);
            #pragma unroll
            for (int k = 0; k < 9; ++k) t[k] = sent2;
            for (int z = ez0; z <= ez1; ++z)
                for (int y = ey0; y <= ey1; ++y)
                    for (int x = ex0; x <= ex1; ++x) {
                        int c2 = (z * GDIM + y) * GDIM + x;
                        int cnt2 = min(g_cnt[c2], CAP);
                        int b2 = c2 * CAP;
                        for (int j = lane; j < cnt2; j += 32) {
                            float4 p = g_bpos[b2 + j];
                            float dot = fmaf(P.x, p.x, fmaf(P.y, p.y, P.z * p.z));
                            float d2  = fmaf(-2.0f, dot, P.w + p.w);
                            insert9(t, d2);
                        }
                    }
            knn = knn_mean(t, lane, &ninth);
            bool full = (ex0 == 0) && (ex1 == 7) && (ey0 == 0) &&
                        (ey1 == 7) && (ez0 == 0) && (ez1 == 7);
            done = (ninth < sent2) || full;
        }

        if (lane == 0) {
            Ap += asum;
            Cp += acnt;
            Dp += fabsf(knn - 0.01f) * opacity[myid];
            Fp += g_flat[myid];
        }
    }

    if (lane == 0) {
        s_part[warp][0] = Fp; s_part[warp][1] = Dp;
        s_part[warp][2] = Ap; s_part[warp][3] = Cp;
    }
    __syncthreads();

    if (tid == 0) {
        float4 bp = make_float4(0.0f, 0.0f, 0.0f, 0.0f);
        #pragma unroll
        for (int w = 0; w < 8; ++w) {
            bp.x += s_part[w][0]; bp.y += s_part[w][1];
            bp.z += s_part[w][2]; bp.w += s_part[w][3];
        }
        g_part[cell] = bp;
        __threadfence();
        int old = atomicAdd(&g_done, 1);
        s_is_last = (old == NCELLS - 1) ? 1 : 0;
    }
    __syncthreads();

    // last block to finish: deterministic fixed-tree reduction + cleanup
    if (s_is_last) {
        float F = 0.0f, D = 0.0f, A = 0.0f, C = 0.0f;
        #pragma unroll
        for (int k = 0; k < NCELLS / 256; ++k) {
            float4 v = __ldcg(&g_part[tid + k * 256]);
            F += v.x; D += v.y; A += v.z; C += v.w;
        }
        #pragma unroll
        for (int o = 16; o > 0; o >>= 1) {
            F += __shfl_down_sync(0xffffffffu, F, o);
            D += __shfl_down_sync(0xffffffffu, D, o);
            A += __shfl_down_sync(0xffffffffu, A, o);
            C += __shfl_down_sync(0xffffffffu, C, o);
        }
        if (lane == 0) { s_red[warp][0] = F; s_red[warp][1] = D; s_red[warp][2] = A; s_red[warp][3] = C; }
        __syncthreads();
        if (tid == 0) {
            F = 0.0f; D = 0.0f; A = 0.0f; C = 0.0f;
            #pragma unroll
            for (int w = 0; w < 8; ++w) {
                F += s_red[w][0]; D += s_red[w][1];
                A += s_red[w][2]; C += s_red[w][3];
            }
            float flatness_loss  = -(F / (float)N_PTS);
            float alignment_loss = (C > 0.0f) ? (A / C) : 0.0f;
            float density_loss   = D / (float)N_PTS;
            out[0] = flatness_loss + 0.5f * alignment_loss + 0.2f * density_loss;
            g_done = 0;
        }
        // restore bucket counters for next graph replay
        g_cnt[tid] = 0;
        g_cnt[tid + 256] = 0;
    }
}

// ---------------- launch ----------------
extern "C" void kernel_launch(void* const* d_in, const int* in_sizes, int n_in,
                              void* d_out, int out_size) {
    const float*  positions = (const float*)d_in[0];
    const float4* rotations = (const float4*)d_in[1];
    const float*  scales    = (const float*)d_in[2];
    const float*  opacity   = (const float*)d_in[3];
    float* out = (float*)d_out;

    scatter_k<<<N_PTS / 256, 256>>>(positions, rotations, scales);
    main_k<<<NCELLS, 256>>>(opacity, out);
}